// round 7
// baseline (speedup 1.0000x reference)
#include <cuda_runtime.h>
#include <math.h>

#define B 64
#define C 256
#define KTOP 8
#define NT 64
#define NMAX 20000
#define TN 128
#define NBLK_MAX ((NMAX + TN - 1) / TN)        // 157
#define CAND_MAX (NBLK_MAX * 8)                // 1256 candidates per row

// -------- device scratch (no allocations allowed) --------
__device__ float g_qn[B * C];
__device__ float g_sinv[NMAX];
__device__ unsigned long long g_cand[B * CAND_MAX];
__device__ unsigned long long g_cand2[B * 32];
__device__ int g_topidx[B * KTOP];

typedef unsigned long long u64;

__device__ __forceinline__ unsigned fmono(float f) {
    unsigned u = __float_as_uint(f);
    return (u & 0x80000000u) ? ~u : (u | 0x80000000u);
}

// ---------------- packed f32x2 helpers (sims kernel) ----------------
__device__ __forceinline__ u64 pack2(float lo, float hi) {
    u64 r;
    asm("mov.b64 %0, {%1, %2};" : "=l"(r) : "r"(__float_as_uint(lo)), "r"(__float_as_uint(hi)));
    return r;
}
__device__ __forceinline__ u64 dup2(float v) { return pack2(v, v); }
__device__ __forceinline__ void unpack2(u64 in, float& lo, float& hi) {
    unsigned a, b;
    asm("mov.b64 {%0, %1}, %2;" : "=r"(a), "=r"(b) : "l"(in));
    lo = __uint_as_float(a);
    hi = __uint_as_float(b);
}
__device__ __forceinline__ u64 fma2(u64 a, u64 b, u64 c) {
    u64 d;
    asm("fma.rn.f32x2 %0, %1, %2, %3;" : "=l"(d) : "l"(a), "l"(b), "l"(c));
    return d;
}

// ---------------- tf32 helpers ----------------
__device__ __forceinline__ unsigned to_tf32(float x) {
    unsigned r;
    asm("cvt.rna.tf32.f32 %0, %1;" : "=r"(r) : "f"(x));
    return r;
}
__device__ __forceinline__ void split_tf32(float x, unsigned& hi, unsigned& lo) {
    hi = to_tf32(x);
    float r = x - __uint_as_float(hi);
    lo = to_tf32(r);
}
__device__ __forceinline__ void mma_tf32(float* d, const unsigned* a, unsigned b0, unsigned b1) {
    asm volatile(
        "mma.sync.aligned.m16n8k8.row.col.f32.tf32.tf32.f32 "
        "{%0,%1,%2,%3}, {%4,%5,%6,%7}, {%8,%9}, {%0,%1,%2,%3};"
        : "+f"(d[0]), "+f"(d[1]), "+f"(d[2]), "+f"(d[3])
        : "r"(a[0]), "r"(a[1]), "r"(a[2]), "r"(a[3]), "r"(b0), "r"(b1));
}

// ======================= K1a: normalize query rows =======================
__global__ void qnorm_kernel(const float* __restrict__ q) {
    int b = blockIdx.x, t = threadIdx.x;
    float v = q[b * C + t];
    float ss = v * v;
    #pragma unroll
    for (int o = 16; o; o >>= 1) ss += __shfl_xor_sync(~0u, ss, o);
    __shared__ float ws[8];
    __shared__ float sc;
    if ((t & 31) == 0) ws[t >> 5] = ss;
    __syncthreads();
    if (t == 0) {
        float s = 0.f;
        #pragma unroll
        for (int i = 0; i < 8; i++) s += ws[i];
        sc = 1.f / fmaxf(sqrtf(s), 1e-12f);
    }
    __syncthreads();
    g_qn[b * C + t] = v * sc;
}

// ======================= K1b: summary inverse norms ======================
__global__ void sinv_kernel(const float* __restrict__ s, int n) {
    int warp = (blockIdx.x * blockDim.x + threadIdx.x) >> 5;
    int lane = threadIdx.x & 31;
    if (warp >= n) return;
    const float4* row = (const float4*)(s + (size_t)warp * C);
    float ss = 0.f;
    #pragma unroll
    for (int r = 0; r < 2; r++) {
        float4 v = row[lane + 32 * r];
        ss += v.x * v.x + v.y * v.y + v.z * v.z + v.w * v.w;
    }
    #pragma unroll
    for (int o = 16; o; o >>= 1) ss += __shfl_xor_sync(~0u, ss, o);
    if (lane == 0) g_sinv[warp] = 1.f / fmaxf(sqrtf(ss), 1e-12f);
}

// ============== K2: sims GEMM tile (f32x2) + fused per-block top-8 ======
#define KC 32
#define CE(a, b) { if (v[a] < v[b]) { u64 _t = v[a]; v[a] = v[b]; v[b] = _t; } }

__global__ void sims_kernel(const float* __restrict__ summ, int n) {
    __shared__ float Qs[KC * 65];
    __shared__ __align__(16) float Ss[KC * 130];
    int tid = threadIdx.x;
    int ng = tid & 15, bg = tid >> 4;
    int n0 = blockIdx.x * TN;
    u64 acc2[4][4];
    #pragma unroll
    for (int a = 0; a < 4; a++)
        #pragma unroll
        for (int p = 0; p < 4; p++) acc2[a][p] = 0ull;

    for (int kc = 0; kc < C; kc += KC) {
        #pragma unroll
        for (int r = 0; r < 8; r++) {
            int idx = tid + 256 * r;
            int b = idx >> 5, i = idx & 31;
            Qs[i * 65 + b] = g_qn[b * C + kc + i];
        }
        #pragma unroll
        for (int r = 0; r < 16; r++) {
            int idx = tid + 256 * r;
            int nn = idx >> 5, i = idx & 31;
            int ngl = n0 + nn;
            Ss[i * 130 + nn] = (ngl < n) ? summ[(size_t)ngl * C + kc + i] : 0.f;
        }
        __syncthreads();
        #pragma unroll
        for (int i = 0; i < KC; i++) {
            u64 qp[4], sp[4];
            #pragma unroll
            for (int a = 0; a < 4; a++) qp[a] = dup2(Qs[i * 65 + bg + 16 * a]);
            #pragma unroll
            for (int p = 0; p < 4; p++)
                sp[p] = *(const u64*)&Ss[i * 130 + 2 * ng + 32 * p];
            #pragma unroll
            for (int a = 0; a < 4; a++)
                #pragma unroll
                for (int p = 0; p < 4; p++) acc2[a][p] = fma2(qp[a], sp[p], acc2[a][p]);
        }
        __syncthreads();
    }

    float si[4][2];
    int nn[4];
    #pragma unroll
    for (int p = 0; p < 4; p++) {
        nn[p] = n0 + 2 * ng + 32 * p;
        si[p][0] = (nn[p] < n) ? g_sinv[nn[p]] : 0.f;
        si[p][1] = (nn[p] + 1 < n) ? g_sinv[nn[p] + 1] : 0.f;
    }

    #pragma unroll
    for (int a = 0; a < 4; a++) {
        int row = bg + 16 * a;
        u64 v[8];
        #pragma unroll
        for (int p = 0; p < 4; p++) {
            float lo, hi;
            unpack2(acc2[a][p], lo, hi);
            v[2 * p]     = (nn[p] < n)
                ? (((u64)fmono(lo * si[p][0]) << 32) | (unsigned)(~(unsigned)nn[p])) : 0ull;
            v[2 * p + 1] = (nn[p] + 1 < n)
                ? (((u64)fmono(hi * si[p][1]) << 32) | (unsigned)(~(unsigned)(nn[p] + 1))) : 0ull;
        }
        CE(0,1) CE(2,3) CE(4,5) CE(6,7)
        CE(0,2) CE(1,3) CE(4,6) CE(5,7)
        CE(1,2) CE(5,6) CE(0,4) CE(3,7)
        CE(1,5) CE(2,6)
        CE(1,4) CE(3,6)
        CE(2,4) CE(3,5)
        CE(3,4)
        #pragma unroll
        for (int o = 1; o < 16; o <<= 1) {
            u64 w[8];
            #pragma unroll
            for (int c = 0; c < 8; c++) w[c] = __shfl_xor_sync(~0u, v[c], o);
            u64 m[8];
            int ii = 0, jj = 0;
            #pragma unroll
            for (int k = 0; k < 8; k++) {
                bool take = v[ii] >= w[jj];
                m[k] = take ? v[ii] : w[jj];
                ii += take ? 1 : 0;
                jj += take ? 0 : 1;
            }
            #pragma unroll
            for (int c = 0; c < 8; c++) v[c] = m[c];
        }
        if (ng == 0) {
            u64* dst = g_cand + (size_t)row * CAND_MAX + (size_t)blockIdx.x * 8;
            #pragma unroll
            for (int c = 0; c < 8; c++) dst[c] = v[c];
        }
    }
}

// ---------------- shared merge helpers for top-k ----------------
__device__ __forceinline__ void warp_merge8(u64* v, int width) {
    for (int o = 1; o < width; o <<= 1) {
        u64 w[8];
        #pragma unroll
        for (int c = 0; c < 8; c++) w[c] = __shfl_xor_sync(~0u, v[c], o);
        u64 m[8];
        int ii = 0, jj = 0;
        #pragma unroll
        for (int k = 0; k < 8; k++) {
            bool take = v[ii] >= w[jj];
            m[k] = take ? v[ii] : w[jj];
            ii += take ? 1 : 0;
            jj += take ? 0 : 1;
        }
        #pragma unroll
        for (int c = 0; c < 8; c++) v[c] = m[c];
    }
}

// ============ K3a: partial top-8 (grid 64 x 4, 128 threads) =============
__global__ void topk_part_kernel(int ncand) {
    int b = blockIdx.x, part = blockIdx.y, tid = threadIdx.x;
    int chunk = (ncand + 3) / 4;
    int lo = part * chunk, hi = min(lo + chunk, ncand);
    const u64* cand = g_cand + (size_t)b * CAND_MAX;
    u64 v[8];
    #pragma unroll
    for (int i = 0; i < 8; i++) v[i] = 0ull;
    for (int j = lo + tid; j < hi; j += 128) {
        u64 x = cand[j];
        if (x > v[7]) {
            int pos = 8;
            #pragma unroll
            for (int i = 7; i >= 0; i--) if (x > v[i]) pos = i;
            for (int i = 7; i > pos; i--) v[i] = v[i - 1];
            v[pos] = x;
        }
    }
    warp_merge8(v, 32);
    __shared__ u64 wl[4][8];
    int warp = tid >> 5, lane = tid & 31;
    if (lane == 0)
        #pragma unroll
        for (int c = 0; c < 8; c++) wl[warp][c] = v[c];
    __syncthreads();
    if (tid == 0) {
        u64 f[8];
        #pragma unroll
        for (int i = 0; i < 8; i++) f[i] = wl[0][i];
        for (int wr = 1; wr < 4; wr++) {
            for (int c = 0; c < 8; c++) {
                u64 x = wl[wr][c];
                if (x > f[7]) {
                    int pos = 8;
                    #pragma unroll
                    for (int i = 7; i >= 0; i--) if (x > f[i]) pos = i;
                    for (int i = 7; i > pos; i--) f[i] = f[i - 1];
                    f[pos] = x;
                } else break;
            }
        }
        u64* dst = g_cand2 + (size_t)(b * 4 + part) * 8;
        #pragma unroll
        for (int c = 0; c < 8; c++) dst[c] = f[c];
    }
}

// ============ K3b: final top-8 (grid 64, 32 threads) ====================
__global__ void topk_final_kernel() {
    int b = blockIdx.x, lane = threadIdx.x;
    u64 v[8];
    v[0] = g_cand2[(size_t)b * 32 + lane];
    #pragma unroll
    for (int i = 1; i < 8; i++) v[i] = 0ull;
    warp_merge8(v, 32);
    if (lane == 0)
        #pragma unroll
        for (int k = 0; k < KTOP; k++)
            g_topidx[b * KTOP + k] = (int)(~(unsigned)(v[k] & 0xFFFFFFFFull));
}

// ===== K4: split-tf32 mma.sync gather + Linear + LayerNorm + gate =======
// Block = ONE (b,k) tile: M=64 tokens x N=256 outs, K=256 in 8 chunks of 32.
// 3 passes: Xh*Wh + Xh*Wl + Xl*Wh. 8 warps in 2x4 grid:
//   warp w: rows tb=(w&1)*32 (2 m16 tiles), cols nb=(w>>1)*64 (8 n8 tiles).
#define APS 17
#define A_F2 (64 * APS)        // 1088
#define W_F2 (256 * APS)       // 4352
#define SMEM_MMA ((2 * A_F2 + 2 * W_F2) * 8 + 768 * 4 + 64 * 4 * 8)

__global__ void __launch_bounds__(256, 2) proj_mma_kernel(
    const float* __restrict__ tmpl, const float* __restrict__ wproj,
    const float* __restrict__ bproj, const float* __restrict__ gamma,
    const float* __restrict__ beta, const float* __restrict__ glog,
    float* __restrict__ out) {
    extern __shared__ __align__(16) float2 smf[];
    float2* Ah = smf;
    float2* Al = Ah + A_F2;
    float2* Wh = Al + A_F2;
    float2* Wl = Wh + W_F2;
    float*  lnS = (float*)(Wl + W_F2);      // 768 floats: bias|gamma|beta
    float2* red = (float2*)(lnS + 768);     // [row][cg] 64*4 float2

    int tid = threadIdx.x, wid = tid >> 5, lane = tid & 31;
    int blk = blockIdx.x;

    lnS[tid] = bproj[tid];
    lnS[256 + tid] = gamma[tid];
    lnS[512 + tid] = beta[tid];

    int bank = g_topidx[blk];

    // X fill assignment: 4 threads per row, 8 k each (one s-slice)
    int xrow = tid >> 2, xs = tid & 3;
    const float* xsrc = tmpl + ((size_t)bank * NT + xrow) * C;

    float acc[2][8][4];
    #pragma unroll
    for (int mi = 0; mi < 2; mi++)
        #pragma unroll
        for (int nt = 0; nt < 8; nt++)
            #pragma unroll
            for (int e = 0; e < 4; e++) acc[mi][nt][e] = 0.f;

    int tb = (wid & 1) * 32;
    int nb = (wid >> 1) * 64;
    int cg = wid >> 1;

    for (int ch = 0; ch < 8; ch++) {
        int kc = ch * 32;
        __syncthreads();  // previous chunk's MMAs done before refill
        // ---- X fill (8 values = one s-slice) ----
        {
            const float4* s4 = (const float4*)(xsrc + kc + xs * 8);
            float4 v0 = s4[0], v1 = s4[1];
            float xv[8] = {v0.x, v0.y, v0.z, v0.w, v1.x, v1.y, v1.z, v1.w};
            #pragma unroll
            for (int c = 0; c < 4; c++) {
                unsigned h0, l0, h1, l1;
                split_tf32(xv[c], h0, l0);
                split_tf32(xv[c + 4], h1, l1);
                int idx = xrow * APS + xs * 4 + c;
                Ah[idx] = make_float2(__uint_as_float(h0), __uint_as_float(h1));
                Al[idx] = make_float2(__uint_as_float(l0), __uint_as_float(l1));
            }
        }
        // ---- W fill (32 values, j = tid), two half-passes ----
        #pragma unroll
        for (int half = 0; half < 2; half++) {
            float wv[16];
            const float4* s4 = (const float4*)(wproj + (size_t)tid * C + kc + half * 16);
            #pragma unroll
            for (int q = 0; q < 4; q++) {
                float4 v = s4[q];
                wv[q * 4 + 0] = v.x; wv[q * 4 + 1] = v.y;
                wv[q * 4 + 2] = v.z; wv[q * 4 + 3] = v.w;
            }
            #pragma unroll
            for (int sl = 0; sl < 2; sl++) {
                int s = half * 2 + sl;
                #pragma unroll
                for (int c = 0; c < 4; c++) {
                    unsigned h0, l0, h1, l1;
                    split_tf32(wv[sl * 8 + c], h0, l0);
                    split_tf32(wv[sl * 8 + c + 4], h1, l1);
                    int idx = tid * APS + s * 4 + c;
                    Wh[idx] = make_float2(__uint_as_float(h0), __uint_as_float(h1));
                    Wl[idx] = make_float2(__uint_as_float(l0), __uint_as_float(l1));
                }
            }
        }
        __syncthreads();
        // ---- MMA: 3 passes x 4 ksteps x (2m x 8n) tiles ----
        #pragma unroll
        for (int pass = 0; pass < 3; pass++) {
            const float2* Ab = (pass == 2) ? Al : Ah;
            const float2* Wb = (pass == 1) ? Wl : Wh;
            #pragma unroll
            for (int s = 0; s < 4; s++) {
                unsigned a[2][4];
                #pragma unroll
                for (int mi = 0; mi < 2; mi++) {
                    int r0 = tb + mi * 16 + (lane >> 2);
                    float2 p0 = Ab[r0 * APS + s * 4 + (lane & 3)];
                    float2 p1 = Ab[(r0 + 8) * APS + s * 4 + (lane & 3)];
                    a[mi][0] = __float_as_uint(p0.x);
                    a[mi][1] = __float_as_uint(p1.x);
                    a[mi][2] = __float_as_uint(p0.y);
                    a[mi][3] = __float_as_uint(p1.y);
                }
                #pragma unroll
                for (int nt = 0; nt < 8; nt++) {
                    int j = nb + nt * 8 + (lane >> 2);
                    float2 bp = Wb[j * APS + s * 4 + (lane & 3)];
                    unsigned b0 = __float_as_uint(bp.x), b1 = __float_as_uint(bp.y);
                    mma_tf32(acc[0][nt], a[0], b0, b1);
                    mma_tf32(acc[1][nt], a[1], b0, b1);
                }
            }
        }
    }
    __syncthreads();

    // ---- epilogue: bias + LayerNorm + gate ----
    float gate = 1.f / (1.f + expf(-glog[0]));
    // partial row sums over this warp's 64-col group
    #pragma unroll
    for (int mi = 0; mi < 2; mi++) {
        #pragma unroll
        for (int rh = 0; rh < 2; rh++) {
            float s1 = 0.f, s2 = 0.f;
            #pragma unroll
            for (int nt = 0; nt < 8; nt++) {
                int c0 = nb + nt * 8 + 2 * (lane & 3);
                float h0 = acc[mi][nt][rh * 2 + 0] + lnS[c0];
                float h1 = acc[mi][nt][rh * 2 + 1] + lnS[c0 + 1];
                s1 += h0 + h1;
                s2 += h0 * h0 + h1 * h1;
            }
            s1 += __shfl_xor_sync(~0u, s1, 1);
            s2 += __shfl_xor_sync(~0u, s2, 1);
            s1 += __shfl_xor_sync(~0u, s1, 2);
            s2 += __shfl_xor_sync(~0u, s2, 2);
            if ((lane & 3) == 0) {
                int row = tb + mi * 16 + rh * 8 + (lane >> 2);
                red[row * 4 + cg] = make_float2(s1, s2);
            }
        }
    }
    __syncthreads();
    #pragma unroll
    for (int mi = 0; mi < 2; mi++) {
        #pragma unroll
        for (int rh = 0; rh < 2; rh++) {
            int row = tb + mi * 16 + rh * 8 + (lane >> 2);
            float2 r0 = red[row * 4 + 0];
            float2 r1 = red[row * 4 + 1];
            float2 r2 = red[row * 4 + 2];
            float2 r3 = red[row * 4 + 3];
            float mu = (r0.x + r1.x + r2.x + r3.x) * (1.f / 256.f);
            float var = (r0.y + r1.y + r2.y + r3.y) * (1.f / 256.f) - mu * mu;
            float rs = rsqrtf(var + 1e-5f);
            float* orow = out + ((size_t)blk * NT + row) * C;
            #pragma unroll
            for (int nt = 0; nt < 8; nt++) {
                int c0 = nb + nt * 8 + 2 * (lane & 3);
                float h0 = acc[mi][nt][rh * 2 + 0] + lnS[c0];
                float h1 = acc[mi][nt][rh * 2 + 1] + lnS[c0 + 1];
                float2 o;
                o.x = ((h0 - mu) * rs * lnS[256 + c0] + lnS[512 + c0]) * gate;
                o.y = ((h1 - mu) * rs * lnS[256 + c0 + 1] + lnS[512 + c0 + 1]) * gate;
                *(float2*)(orow + c0) = o;
            }
        }
    }
}

// ======================= K5: gate output tail ============================
__global__ void gate_kernel(const float* __restrict__ glog, float* __restrict__ out,
                            int out_size) {
    float gate = 1.f / (1.f + expf(-glog[0]));
    int t = threadIdx.x;
    if (out_size >= B * KTOP * NT * C + B)
        out[B * KTOP * NT * C + t] = gate;
}

// ======================= launch ==========================================
extern "C" void kernel_launch(void* const* d_in, const int* in_sizes, int n_in,
                              void* d_out, int out_size) {
    const float* query = (const float*)d_in[0];
    const float* summ  = (const float*)d_in[1];
    const float* tmpl  = (const float*)d_in[2];
    const float* wproj = (const float*)d_in[3];
    const float* bproj = (const float*)d_in[4];
    const float* gamma = (const float*)d_in[5];
    const float* beta  = (const float*)d_in[6];
    const float* glog  = (const float*)d_in[7];
    int n = in_sizes[1] / C;
    float* out = (float*)d_out;
    int nblocks = (n + TN - 1) / TN;

    cudaFuncSetAttribute(proj_mma_kernel,
                         cudaFuncAttributeMaxDynamicSharedMemorySize, SMEM_MMA);

    qnorm_kernel<<<B, 256>>>(query);
    sinv_kernel<<<(n * 32 + 255) / 256, 256>>>(summ, n);
    sims_kernel<<<nblocks, 256>>>(summ, n);
    topk_part_kernel<<<dim3(B, 4), 128>>>(nblocks * 8);
    topk_final_kernel<<<B, 32>>>();
    proj_mma_kernel<<<B * KTOP, 256, SMEM_MMA>>>(tmpl, wproj, bproj, gamma, beta,
                                                 glog, out);
    gate_kernel<<<1, B>>>(glog, out, out_size);
}

// round 11
// speedup vs baseline: 1.6624x; 1.6624x over previous
#include <cuda_runtime.h>
#include <math.h>

#define B 64
#define C 256
#define KTOP 8
#define NT 64
#define NMAX 20000
#define TN 128
#define NBLK_MAX ((NMAX + TN - 1) / TN)        // 157
#define CAND_MAX (NBLK_MAX * 8)                // 1256 candidates per row

// -------- device scratch (no allocations allowed) --------
__device__ float g_qn[B * C];
__device__ float g_sinv[NMAX];
__device__ unsigned long long g_cand[B * CAND_MAX];
__device__ unsigned long long g_cand2[B * 32];
__device__ int g_topidx[B * KTOP];

typedef unsigned long long u64;

__device__ __forceinline__ unsigned fmono(float f) {
    unsigned u = __float_as_uint(f);
    return (u & 0x80000000u) ? ~u : (u | 0x80000000u);
}

// ---------------- packed f32x2 helpers (sims kernel) ----------------
__device__ __forceinline__ u64 pack2(float lo, float hi) {
    u64 r;
    asm("mov.b64 %0, {%1, %2};" : "=l"(r) : "r"(__float_as_uint(lo)), "r"(__float_as_uint(hi)));
    return r;
}
__device__ __forceinline__ u64 dup2(float v) { return pack2(v, v); }
__device__ __forceinline__ void unpack2(u64 in, float& lo, float& hi) {
    unsigned a, b;
    asm("mov.b64 {%0, %1}, %2;" : "=r"(a), "=r"(b) : "l"(in));
    lo = __uint_as_float(a);
    hi = __uint_as_float(b);
}
__device__ __forceinline__ u64 fma2(u64 a, u64 b, u64 c) {
    u64 d;
    asm("fma.rn.f32x2 %0, %1, %2, %3;" : "=l"(d) : "l"(a), "l"(b), "l"(c));
    return d;
}

// ---------------- bf16 split + mma helpers ----------------
// pack (f0, f1) -> bf16x2 {lo=f0, hi=f1}; lo residuals likewise
__device__ __forceinline__ void split_pair(float f0, float f1, unsigned& hp, unsigned& lp) {
    asm("cvt.rn.bf16x2.f32 %0, %1, %2;" : "=r"(hp) : "f"(f1), "f"(f0));
    float f0h = __uint_as_float(hp << 16);
    float f1h = __uint_as_float(hp & 0xffff0000u);
    float r0 = f0 - f0h, r1 = f1 - f1h;
    asm("cvt.rn.bf16x2.f32 %0, %1, %2;" : "=r"(lp) : "f"(r1), "f"(r0));
}
__device__ __forceinline__ void mma_bf16(float* d, const unsigned* a, unsigned b0, unsigned b1) {
    asm volatile(
        "mma.sync.aligned.m16n8k16.row.col.f32.bf16.bf16.f32 "
        "{%0,%1,%2,%3}, {%4,%5,%6,%7}, {%8,%9}, {%0,%1,%2,%3};"
        : "+f"(d[0]), "+f"(d[1]), "+f"(d[2]), "+f"(d[3])
        : "r"(a[0]), "r"(a[1]), "r"(a[2]), "r"(a[3]), "r"(b0), "r"(b1));
}

// ======================= K1a: normalize query rows =======================
__global__ void qnorm_kernel(const float* __restrict__ q) {
    int b = blockIdx.x, t = threadIdx.x;
    float v = q[b * C + t];
    float ss = v * v;
    #pragma unroll
    for (int o = 16; o; o >>= 1) ss += __shfl_xor_sync(~0u, ss, o);
    __shared__ float ws[8];
    __shared__ float sc;
    if ((t & 31) == 0) ws[t >> 5] = ss;
    __syncthreads();
    if (t == 0) {
        float s = 0.f;
        #pragma unroll
        for (int i = 0; i < 8; i++) s += ws[i];
        sc = 1.f / fmaxf(sqrtf(s), 1e-12f);
    }
    __syncthreads();
    g_qn[b * C + t] = v * sc;
}

// ======================= K1b: summary inverse norms ======================
__global__ void sinv_kernel(const float* __restrict__ s, int n) {
    int warp = (blockIdx.x * blockDim.x + threadIdx.x) >> 5;
    int lane = threadIdx.x & 31;
    if (warp >= n) return;
    const float4* row = (const float4*)(s + (size_t)warp * C);
    float ss = 0.f;
    #pragma unroll
    for (int r = 0; r < 2; r++) {
        float4 v = row[lane + 32 * r];
        ss += v.x * v.x + v.y * v.y + v.z * v.z + v.w * v.w;
    }
    #pragma unroll
    for (int o = 16; o; o >>= 1) ss += __shfl_xor_sync(~0u, ss, o);
    if (lane == 0) g_sinv[warp] = 1.f / fmaxf(sqrtf(ss), 1e-12f);
}

// ============== K2: sims GEMM tile (f32x2) + fused per-block top-8 ======
#define KC 32
#define CE(a, b) { if (v[a] < v[b]) { u64 _t = v[a]; v[a] = v[b]; v[b] = _t; } }

__global__ void sims_kernel(const float* __restrict__ summ, int n) {
    __shared__ float Qs[KC * 65];
    __shared__ __align__(16) float Ss[KC * 130];
    int tid = threadIdx.x;
    int ng = tid & 15, bg = tid >> 4;
    int n0 = blockIdx.x * TN;
    u64 acc2[4][4];
    #pragma unroll
    for (int a = 0; a < 4; a++)
        #pragma unroll
        for (int p = 0; p < 4; p++) acc2[a][p] = 0ull;

    for (int kc = 0; kc < C; kc += KC) {
        #pragma unroll
        for (int r = 0; r < 8; r++) {
            int idx = tid + 256 * r;
            int b = idx >> 5, i = idx & 31;
            Qs[i * 65 + b] = g_qn[b * C + kc + i];
        }
        #pragma unroll
        for (int r = 0; r < 16; r++) {
            int idx = tid + 256 * r;
            int nn = idx >> 5, i = idx & 31;
            int ngl = n0 + nn;
            Ss[i * 130 + nn] = (ngl < n) ? summ[(size_t)ngl * C + kc + i] : 0.f;
        }
        __syncthreads();
        #pragma unroll
        for (int i = 0; i < KC; i++) {
            u64 qp[4], sp[4];
            #pragma unroll
            for (int a = 0; a < 4; a++) qp[a] = dup2(Qs[i * 65 + bg + 16 * a]);
            #pragma unroll
            for (int p = 0; p < 4; p++)
                sp[p] = *(const u64*)&Ss[i * 130 + 2 * ng + 32 * p];
            #pragma unroll
            for (int a = 0; a < 4; a++)
                #pragma unroll
                for (int p = 0; p < 4; p++) acc2[a][p] = fma2(qp[a], sp[p], acc2[a][p]);
        }
        __syncthreads();
    }

    float si[4][2];
    int nn[4];
    #pragma unroll
    for (int p = 0; p < 4; p++) {
        nn[p] = n0 + 2 * ng + 32 * p;
        si[p][0] = (nn[p] < n) ? g_sinv[nn[p]] : 0.f;
        si[p][1] = (nn[p] + 1 < n) ? g_sinv[nn[p] + 1] : 0.f;
    }

    #pragma unroll
    for (int a = 0; a < 4; a++) {
        int row = bg + 16 * a;
        u64 v[8];
        #pragma unroll
        for (int p = 0; p < 4; p++) {
            float lo, hi;
            unpack2(acc2[a][p], lo, hi);
            v[2 * p]     = (nn[p] < n)
                ? (((u64)fmono(lo * si[p][0]) << 32) | (unsigned)(~(unsigned)nn[p])) : 0ull;
            v[2 * p + 1] = (nn[p] + 1 < n)
                ? (((u64)fmono(hi * si[p][1]) << 32) | (unsigned)(~(unsigned)(nn[p] + 1))) : 0ull;
        }
        CE(0,1) CE(2,3) CE(4,5) CE(6,7)
        CE(0,2) CE(1,3) CE(4,6) CE(5,7)
        CE(1,2) CE(5,6) CE(0,4) CE(3,7)
        CE(1,5) CE(2,6)
        CE(1,4) CE(3,6)
        CE(2,4) CE(3,5)
        CE(3,4)
        #pragma unroll
        for (int o = 1; o < 16; o <<= 1) {
            u64 w[8];
            #pragma unroll
            for (int c = 0; c < 8; c++) w[c] = __shfl_xor_sync(~0u, v[c], o);
            u64 m[8];
            int ii = 0, jj = 0;
            #pragma unroll
            for (int k = 0; k < 8; k++) {
                bool take = v[ii] >= w[jj];
                m[k] = take ? v[ii] : w[jj];
                ii += take ? 1 : 0;
                jj += take ? 0 : 1;
            }
            #pragma unroll
            for (int c = 0; c < 8; c++) v[c] = m[c];
        }
        if (ng == 0) {
            u64* dst = g_cand + (size_t)row * CAND_MAX + (size_t)blockIdx.x * 8;
            #pragma unroll
            for (int c = 0; c < 8; c++) dst[c] = v[c];
        }
    }
}

// ---------------- shared merge helpers for top-k ----------------
__device__ __forceinline__ void warp_merge8(u64* v, int width) {
    for (int o = 1; o < width; o <<= 1) {
        u64 w[8];
        #pragma unroll
        for (int c = 0; c < 8; c++) w[c] = __shfl_xor_sync(~0u, v[c], o);
        u64 m[8];
        int ii = 0, jj = 0;
        #pragma unroll
        for (int k = 0; k < 8; k++) {
            bool take = v[ii] >= w[jj];
            m[k] = take ? v[ii] : w[jj];
            ii += take ? 1 : 0;
            jj += take ? 0 : 1;
        }
        #pragma unroll
        for (int c = 0; c < 8; c++) v[c] = m[c];
    }
}

// ============ K3a: partial top-8 (grid 64 x 4, 128 threads) =============
__global__ void topk_part_kernel(int ncand) {
    int b = blockIdx.x, part = blockIdx.y, tid = threadIdx.x;
    int chunk = (ncand + 3) / 4;
    int lo = part * chunk, hi = min(lo + chunk, ncand);
    const u64* cand = g_cand + (size_t)b * CAND_MAX;
    u64 v[8];
    #pragma unroll
    for (int i = 0; i < 8; i++) v[i] = 0ull;
    for (int j = lo + tid; j < hi; j += 128) {
        u64 x = cand[j];
        if (x > v[7]) {
            int pos = 8;
            #pragma unroll
            for (int i = 7; i >= 0; i--) if (x > v[i]) pos = i;
            for (int i = 7; i > pos; i--) v[i] = v[i - 1];
            v[pos] = x;
        }
    }
    warp_merge8(v, 32);
    __shared__ u64 wl[4][8];
    int warp = tid >> 5, lane = tid & 31;
    if (lane == 0)
        #pragma unroll
        for (int c = 0; c < 8; c++) wl[warp][c] = v[c];
    __syncthreads();
    if (tid == 0) {
        u64 f[8];
        #pragma unroll
        for (int i = 0; i < 8; i++) f[i] = wl[0][i];
        for (int wr = 1; wr < 4; wr++) {
            for (int c = 0; c < 8; c++) {
                u64 x = wl[wr][c];
                if (x > f[7]) {
                    int pos = 8;
                    #pragma unroll
                    for (int i = 7; i >= 0; i--) if (x > f[i]) pos = i;
                    for (int i = 7; i > pos; i--) f[i] = f[i - 1];
                    f[pos] = x;
                } else break;
            }
        }
        u64* dst = g_cand2 + (size_t)(b * 4 + part) * 8;
        #pragma unroll
        for (int c = 0; c < 8; c++) dst[c] = f[c];
    }
}

// ============ K3b: final top-8 (grid 64, 32 threads) ====================
__global__ void topk_final_kernel() {
    int b = blockIdx.x, lane = threadIdx.x;
    u64 v[8];
    v[0] = g_cand2[(size_t)b * 32 + lane];
    #pragma unroll
    for (int i = 1; i < 8; i++) v[i] = 0ull;
    warp_merge8(v, 32);
    if (lane == 0)
        #pragma unroll
        for (int k = 0; k < KTOP; k++)
            g_topidx[b * KTOP + k] = (int)(~(unsigned)(v[k] & 0xFFFFFFFFull));
}

// ===== K4: split-bf16 m16n8k16 gather + Linear + LayerNorm + gate =======
// Block = ONE (b,k) tile: M=64 x N=256, K=256 in 8 chunks of 32.
// 3 passes: Xh*Wh + Xh*Wl + Xl*Wh. 8 warps (2 row-groups x 4 col-groups).
// Fragments loaded with plain scalar LDS (no ldmatrix). smem rows: 16 kpair
// words padded to stride 20 (all 32 banks hit exactly once per frag load).
#define RSTR 20
#define AH_OFF 0
#define AL_OFF (64 * RSTR * 4)                 // 5120
#define WH_OFF (2 * 64 * RSTR * 4)             // 10240
#define WL_OFF (WH_OFF + 256 * RSTR * 4)       // 30720
#define LN_OFF (WL_OFF + 256 * RSTR * 4)       // 51200
#define RED_OFF (LN_OFF + 768 * 4)             // 54272
#define SMEM_MMA (RED_OFF + 64 * 4 * 8)        // 56320

__global__ void __launch_bounds__(256, 2) proj_mma_kernel(
    const float* __restrict__ tmpl, const float* __restrict__ wproj,
    const float* __restrict__ bproj, const float* __restrict__ gamma,
    const float* __restrict__ beta, const float* __restrict__ glog,
    float* __restrict__ out) {
    extern __shared__ __align__(16) char sm[];
    unsigned* AH = (unsigned*)(sm + AH_OFF);
    unsigned* AL = (unsigned*)(sm + AL_OFF);
    unsigned* WH = (unsigned*)(sm + WH_OFF);
    unsigned* WL = (unsigned*)(sm + WL_OFF);
    float* lnS = (float*)(sm + LN_OFF);
    float2* red = (float2*)(sm + RED_OFF);

    int tid = threadIdx.x, wid = tid >> 5, lane = tid & 31;
    int blk = blockIdx.x;

    lnS[tid] = bproj[tid];
    lnS[256 + tid] = gamma[tid];
    lnS[512 + tid] = beta[tid];

    int bank = g_topidx[blk];
    // X fill: thread -> row=tid>>2 (0..63), quad=tid&3 (8 k values)
    int xrow = tid >> 2, xq = tid & 3;
    const float* xsrc = tmpl + ((size_t)bank * NT + xrow) * C + xq * 8;

    float acc[2][8][4];
    #pragma unroll
    for (int mi = 0; mi < 2; mi++)
        #pragma unroll
        for (int nt = 0; nt < 8; nt++)
            #pragma unroll
            for (int e = 0; e < 4; e++) acc[mi][nt][e] = 0.f;

    int tb = (wid & 1) * 32;
    int nb = (wid >> 1) * 64;
    int cg = wid >> 1;
    int fr = lane >> 2, fk = lane & 3;   // fragment row-group / kpair index

    for (int ch = 0; ch < 8; ch++) {
        int kc = ch * 32;
        __syncthreads();  // prev chunk's MMAs done before refill
        // ---- X fill: 8 floats -> 4 hi + 4 lo kpairs ----
        {
            const float4* s4 = (const float4*)(xsrc + kc);
            float4 v0 = s4[0], v1 = s4[1];
            unsigned h[4], l[4];
            split_pair(v0.x, v0.y, h[0], l[0]);
            split_pair(v0.z, v0.w, h[1], l[1]);
            split_pair(v1.x, v1.y, h[2], l[2]);
            split_pair(v1.z, v1.w, h[3], l[3]);
            int off = xrow * RSTR + xq * 4;
            *(uint4*)(AH + off) = make_uint4(h[0], h[1], h[2], h[3]);
            *(uint4*)(AL + off) = make_uint4(l[0], l[1], l[2], l[3]);
        }
        // ---- W fill: j = tid, 32 floats, processed 8 at a time ----
        {
            const float4* s4 = (const float4*)(wproj + (size_t)tid * C + kc);
            #pragma unroll
            for (int q = 0; q < 4; q++) {
                float4 v0 = s4[2 * q], v1 = s4[2 * q + 1];
                unsigned h[4], l[4];
                split_pair(v0.x, v0.y, h[0], l[0]);
                split_pair(v0.z, v0.w, h[1], l[1]);
                split_pair(v1.x, v1.y, h[2], l[2]);
                split_pair(v1.z, v1.w, h[3], l[3]);
                int off = tid * RSTR + q * 4;
                *(uint4*)(WH + off) = make_uint4(h[0], h[1], h[2], h[3]);
                *(uint4*)(WL + off) = make_uint4(l[0], l[1], l[2], l[3]);
            }
        }
        __syncthreads();
        // ---- MMA: 3 passes x 2 k16-steps x (2m x 8n) tiles, scalar LDS ----
        #pragma unroll
        for (int pass = 0; pass < 3; pass++) {
            const unsigned* Ab = (pass == 2) ? AL : AH;
            const unsigned* Wb = (pass == 1) ? WL : WH;
            #pragma unroll
            for (int s = 0; s < 2; s++) {
                int sk = s * 8 + fk;
                unsigned a[2][4];
                #pragma unroll
                for (int mi = 0; mi < 2; mi++) {
                    int r0 = tb + mi * 16 + fr;
                    a[mi][0] = Ab[r0 * RSTR + sk];
                    a[mi][1] = Ab[(r0 + 8) * RSTR + sk];
                    a[mi][2] = Ab[r0 * RSTR + sk + 4];
                    a[mi][3] = Ab[(r0 + 8) * RSTR + sk + 4];
                }
                #pragma unroll
                for (int nt = 0; nt < 8; nt++) {
                    int j = nb + nt * 8 + fr;
                    unsigned b0 = Wb[j * RSTR + sk];
                    unsigned b1 = Wb[j * RSTR + sk + 4];
                    mma_bf16(acc[0][nt], a[0], b0, b1);
                    mma_bf16(acc[1][nt], a[1], b0, b1);
                }
            }
        }
    }
    __syncthreads();

    // ---- epilogue: bias + LayerNorm + gate (identical to passing R7) ----
    float gate = 1.f / (1.f + expf(-glog[0]));
    #pragma unroll
    for (int mi = 0; mi < 2; mi++) {
        #pragma unroll
        for (int rh = 0; rh < 2; rh++) {
            float s1 = 0.f, s2 = 0.f;
            #pragma unroll
            for (int nt = 0; nt < 8; nt++) {
                int c0 = nb + nt * 8 + 2 * (lane & 3);
                float h0 = acc[mi][nt][rh * 2 + 0] + lnS[c0];
                float h1 = acc[mi][nt][rh * 2 + 1] + lnS[c0 + 1];
                s1 += h0 + h1;
                s2 += h0 * h0 + h1 * h1;
            }
            s1 += __shfl_xor_sync(~0u, s1, 1);
            s2 += __shfl_xor_sync(~0u, s2, 1);
            s1 += __shfl_xor_sync(~0u, s1, 2);
            s2 += __shfl_xor_sync(~0u, s2, 2);
            if ((lane & 3) == 0) {
                int row = tb + mi * 16 + rh * 8 + (lane >> 2);
                red[row * 4 + cg] = make_float2(s1, s2);
            }
        }
    }
    __syncthreads();
    #pragma unroll
    for (int mi = 0; mi < 2; mi++) {
        #pragma unroll
        for (int rh = 0; rh < 2; rh++) {
            int row = tb + mi * 16 + rh * 8 + (lane >> 2);
            float2 r0 = red[row * 4 + 0];
            float2 r1 = red[row * 4 + 1];
            float2 r2 = red[row * 4 + 2];
            float2 r3 = red[row * 4 + 3];
            float mu = (r0.x + r1.x + r2.x + r3.x) * (1.f / 256.f);
            float var = (r0.y + r1.y + r2.y + r3.y) * (1.f / 256.f) - mu * mu;
            float rs = rsqrtf(var + 1e-5f);
            float* orow = out + ((size_t)blk * NT + row) * C;
            #pragma unroll
            for (int nt = 0; nt < 8; nt++) {
                int c0 = nb + nt * 8 + 2 * (lane & 3);
                float h0 = acc[mi][nt][rh * 2 + 0] + lnS[c0];
                float h1 = acc[mi][nt][rh * 2 + 1] + lnS[c0 + 1];
                float2 o;
                o.x = ((h0 - mu) * rs * lnS[256 + c0] + lnS[512 + c0]) * gate;
                o.y = ((h1 - mu) * rs * lnS[256 + c0 + 1] + lnS[512 + c0 + 1]) * gate;
                *(float2*)(orow + c0) = o;
            }
        }
    }
}

// ======================= K5: gate output tail ============================
__global__ void gate_kernel(const float* __restrict__ glog, float* __restrict__ out,
                            int out_size) {
    float gate = 1.f / (1.f + expf(-glog[0]));
    int t = threadIdx.x;
    if (out_size >= B * KTOP * NT * C + B)
        out[B * KTOP * NT * C + t] = gate;
}

// ======================= launch ==========================================
extern "C" void kernel_launch(void* const* d_in, const int* in_sizes, int n_in,
                              void* d_out, int out_size) {
    const float* query = (const float*)d_in[0];
    const float* summ  = (const float*)d_in[1];
    const float* tmpl  = (const float*)d_in[2];
    const float* wproj = (const float*)d_in[3];
    const float* bproj = (const float*)d_in[4];
    const float* gamma = (const float*)d_in[5];
    const float* beta  = (const float*)d_in[6];
    const float* glog  = (const float*)d_in[7];
    int n = in_sizes[1] / C;
    float* out = (float*)d_out;
    int nblocks = (n + TN - 1) / TN;

    cudaFuncSetAttribute(proj_mma_kernel,
                         cudaFuncAttributeMaxDynamicSharedMemorySize, SMEM_MMA);

    qnorm_kernel<<<B, 256>>>(query);
    sinv_kernel<<<(n * 32 + 255) / 256, 256>>>(summ, n);
    sims_kernel<<<nblocks, 256>>>(summ, n);
    topk_part_kernel<<<dim3(B, 4), 128>>>(nblocks * 8);
    topk_final_kernel<<<B, 32>>>();
    proj_mma_kernel<<<B * KTOP, 256, SMEM_MMA>>>(tmpl, wproj, bproj, gamma, beta,
                                                 glog, out);
    gate_kernel<<<1, B>>>(glog, out, out_size);
}